// round 16
// baseline (speedup 1.0000x reference)
#include <cuda_runtime.h>
#include <stdint.h>
#include <math.h>

// Problem constants (fixed shapes: scores (128, 4096, 2))
#define NN   4096
#define BSZ  128
#define ENS  2
#define BE   256           // BSZ*ENS
#define KK   32
#define NEGC (-1e30f)
#define HALF_OUT 1048576   // 128*4096*2
#define NCHUNK 32
#define CLEN   128         // NN / NCHUNK
#define NSLICE 4
#define SLEN   1024        // NN / NSLICE
#define FULLM  0xffffffffu
#define BK_BLK 32          // chain blocks: 4 warps x 2 b each = 8 b/block

// ---------------- scratch (static device memory) ----------------
__device__ float    g_B[(size_t)(NN + 1) * BE * KK]; // B[i][b][j-1]
__device__ unsigned g_mask[(size_t)BE * NN];         // inclusion masks [b*NN + i]
__device__ float    g_CE[(size_t)BE * NCHUNK * KK];  // chunk ESPs
__device__ float    g_BD[(size_t)BE * NCHUNK * KK];  // chunk boundary prefixes
__device__ float    g_M[(size_t)BE * NN];            // unnormalized marginals [b][i]
__device__ float    g_E[(size_t)BE * KK];            // backward state between slices
__device__ float    g_off[BE];                       // log e_31 (early normalizer)
__device__ float    g_logZ[BE];                      // exact log e_32
__device__ unsigned g_bits[(size_t)BE * (NN / 32)];  // sampled bits
// sampler chunk-function tables (chunks 32..127)
__device__ unsigned g_sampBits[(size_t)BE * 128 * 32];
__device__ unsigned g_sampMap[(size_t)BE * 128 * 32];

// ---------------- threefry2x32, key = (0, 42) ----------------
__device__ __forceinline__ uint32_t tf_bits(uint32_t lo)
{
    uint32_t x0 = 0u;
    uint32_t x1 = lo;
    const uint32_t ks0 = 0u, ks1 = 42u, ks2 = 0x1BD11BF0u;
    x0 += ks0; x1 += ks1;
#define TFR(r) { x0 += x1; x1 = (x1 << (r)) | (x1 >> (32 - (r))); x1 ^= x0; }
    TFR(13) TFR(15) TFR(26) TFR(6)   x0 += ks1; x1 += ks2 + 1u;
    TFR(17) TFR(29) TFR(16) TFR(24)  x0 += ks2; x1 += ks0 + 2u;
    TFR(13) TFR(15) TFR(26) TFR(6)   x0 += ks0; x1 += ks1 + 3u;
    TFR(17) TFR(29) TFR(16) TFR(24)  x0 += ks1; x1 += ks2 + 4u;
    TFR(13) TFR(15) TFR(26) TFR(6)   x0 += ks2; x1 += ks0 + 5u;
#undef TFR
    return x0 ^ x1;
}

// EXACT logaddexp (libdevice — bitwise path for sampling masks)
__device__ __forceinline__ float logaddexpf32(float x, float y)
{
    float d = x - y;
    return fmaxf(x, y) + log1pf(expf(-fabsf(d)));
}

// Fast logaddexp (marginals path, 1e-3 tolerance)
__device__ __forceinline__ float logaddexp_fast(float x, float y)
{
    float d = x - y;
    return fmaxf(x, y) + __logf(1.0f + __expf(-fabsf(d)));
}

// 16-bit -> even-bit spread (Morton half-interleave)
__device__ __forceinline__ unsigned spread16(unsigned x)
{
    x = (x | (x << 8)) & 0x00FF00FFu;
    x = (x | (x << 4)) & 0x0F0F0F0Fu;
    x = (x | (x << 2)) & 0x33333333u;
    x = (x | (x << 1)) & 0x55555555u;
    return x;
}

// ---------------- backward slice: pair-slot layout, 2 b per warp ----------------
// Sub-lane sl = lane&15 holds log e_{2sl+1} (eA) and log e_{2sl+2} (eB).
// Lanes 0-15 serve b0, lanes 16-31 serve b1. Per (i,j) arithmetic identical to
// the 1-slot version (both slots updated from pre-step values via the same
// exact logaddexp) -> g_B (same column layout) and masks bit-exact. The j-1
// operand for eB is a local register; only eA needs the cross-lane shfl, whose
// latency hides under the independent eB LAE.
__device__ void backward_slice(const float* __restrict__ scores, int s)
{
    int lane = threadIdx.x & 31;
    int sl   = lane & 15;
    int half = lane >> 4;                       // 0: b0, 1: b1
    int b = blockIdx.x * 8 + (threadIdx.x >> 5) * 2 + half;
    const int bz = b >> 1, e = b & 1;
    const float* thbase = scores + (size_t)bz * (NN * ENS) + e;

    float eA, eB;
    if (s == 0) {
        eA = eB = NEGC;
        *(float2*)&g_B[((size_t)NN * BE + b) * KK + 2 * sl] = make_float2(NEGC, NEGC);
    } else {
        float2 v = *(const float2*)&g_E[(size_t)b * KK + 2 * sl];
        eA = v.x; eB = v.y;
    }

    int blk_hi = (NN / 32) - 32 * s;        // exclusive
    int blk_lo = blk_hi - 32;

    // theta registers: th for i = base+sl (thv0) and base+16+sl (thv1), own b
    float thv0 = thbase[2 * ((blk_hi - 1) * 32 + sl)];
    float thv1 = thbase[2 * ((blk_hi - 1) * 32 + 16 + sl)];

    for (int blk = blk_hi - 1; blk >= blk_lo; --blk) {
        int base = blk * 32;
        float tn0 = 0.0f, tn1 = 0.0f;
        if (blk > blk_lo) {
            tn0 = thbase[2 * ((blk - 1) * 32 + sl)];
            tn1 = thbase[2 * ((blk - 1) * 32 + 16 + sl)];
        }
        // uniforms (bit-identical index i*BE + b), off chain
        uint32_t r0 = tf_bits((uint32_t)((base + sl) * BE + b));
        uint32_t r1 = tf_bits((uint32_t)((base + 16 + sl) * BE + b));
        float uv0 = fmaxf(__uint_as_float((r0 >> 9) | 0x3f800000u) - 1.0f, 0.0f);
        float uv1 = fmaxf(__uint_as_float((r1 >> 9) | 0x3f800000u) - 1.0f, 0.0f);

#pragma unroll
        for (int g8 = 3; g8 >= 0; --g8) {
            float lqA[8], lqB[8];
            // chain segment: 8 exact steps, 2 independent LAEs each
#pragma unroll
            for (int t = 7; t >= 0; --t) {
                int ii = g8 * 8 + t;
                int srcl = (lane & 16) | (ii & 15);
                float th = __shfl_sync(FULLM, (ii & 16) ? thv1 : thv0, srcl);
                float rem = __shfl_up_sync(FULLM, eB, 1);   // e_{2sl} (old)
                if (sl == 0) rem = 0.0f;                    // e_0 = log 1
                float shA = rem + th;                       // j = 2sl+1
                float shB = eA + th;                        // j = 2sl+2 (old eA)
                float nA = logaddexpf32(eA, shA);           // EXACT
                float nB = logaddexpf32(eB, shB);           // EXACT
                lqA[t] = shA - nA;
                lqB[t] = shB - nB;
                eA = nA; eB = nB;
                *(float2*)&g_B[((size_t)(base + ii) * BE + b) * KK + 2 * sl] =
                    make_float2(nA, nB);
            }
            // deferred mask generation (off critical path, bit-exact assembly)
#pragma unroll
            for (int t = 7; t >= 0; --t) {
                int ii = g8 * 8 + t;
                int srcl = (lane & 16) | (ii & 15);
                float u = __shfl_sync(FULLM, (ii & 16) ? uv1 : uv0, srcl);
                float qA = expf(fminf(lqA[t], 0.0f));
                float qB = expf(fminf(lqB[t], 0.0f));
                unsigned bA = __ballot_sync(FULLM, u < qA);  // bits: j odd
                unsigned bB = __ballot_sync(FULLM, u < qB);  // bits: j even
                if (sl == 0) {                // lanes 0 (b0) and 16 (b1)
                    unsigned a16 = half ? (bA >> 16) : (bA & 0xFFFFu);
                    unsigned b16 = half ? (bB >> 16) : (bB & 0xFFFFu);
                    // j=2sl+1 -> bit 2sl (even), j=2sl+2 -> bit 2sl+1 (odd)
                    g_mask[(size_t)b * NN + base + ii] =
                        spread16(a16) | (spread16(b16) << 1);
                }
            }
        }
        thv0 = tn0; thv1 = tn1;
    }

    if (s < NSLICE - 1) {
        *(float2*)&g_E[(size_t)b * KK + 2 * sl] = make_float2(eA, eB);
    } else {
        float lz = __shfl_sync(FULLM, eB, (lane & 16) | 15);  // e_32 per half
        if (sl == 0) g_logZ[b] = lz;
    }
}

// ---------------- sampler chunk-function evaluation (32-chunk bands) ----------------
__device__ void samp_chunk(int xb, int cbase)
{
    int lane = threadIdx.x & 31;
    int item = xb * 4 + (threadIdx.x >> 5);   // 0..8191
    int b = item >> 5;
    int c = cbase + (item & 31);

    unsigned mv = g_mask[(size_t)b * NN + c * 32 + lane];  // coalesced
    unsigned r = (unsigned)(lane + 1);
    unsigned w = 0u;
#pragma unroll
    for (int ii = 0; ii < 32; ++ii) {
        unsigned m = __shfl_sync(FULLM, mv, ii);
        unsigned incl = r ? ((m >> (r - 1u)) & 1u) : 0u;
        r -= incl;
        w |= incl << ii;
    }
    g_sampBits[((size_t)b * 128 + c) * 32 + lane] = w;
    g_sampMap[((size_t)b * 128 + c) * 32 + lane] = r;
}

// ---------------- sampler composition (hybrid): warp per b ----------------
__device__ void comp_hybrid(int xb)
{
    int lane = threadIdx.x & 31;
    int b = xb * 4 + (threadIdx.x >> 5);
    const unsigned* mp = &g_sampMap[(size_t)b * 128 * 32];
    const unsigned* bp = &g_sampBits[(size_t)b * 128 * 32];

    unsigned r = KK;   // warp-uniform live state

    for (int c = 0; c < 32; ++c) {
        unsigned mv = g_mask[(size_t)b * NN + c * 32 + lane];
        unsigned rr = (unsigned)(lane + 1);
        unsigned w = 0u;
#pragma unroll
        for (int ii = 0; ii < 32; ++ii) {
            unsigned m = __shfl_sync(FULLM, mv, ii);
            unsigned incl = rr ? ((m >> (rr - 1u)) & 1u) : 0u;
            rr -= incl;
            w |= incl << ii;
        }
        unsigned idx = r ? (r - 1u) : 0u;
        unsigned bits = __shfl_sync(FULLM, w, idx);
        unsigned rn   = __shfl_sync(FULLM, rr, idx);
        if (!r) { bits = 0u; rn = 0u; }
        if (lane == 0) g_bits[(size_t)b * 128 + c] = bits;
        r = rn;
    }

#pragma unroll 4
    for (int c = 32; c < 128; ++c) {
        unsigned mapv = mp[c * 32 + lane];
        unsigned bitv = bp[c * 32 + lane];
        unsigned idx = r ? (r - 1u) : 0u;
        unsigned bits = __shfl_sync(FULLM, bitv, idx);
        unsigned rn   = __shfl_sync(FULLM, mapv, idx);
        if (!r) { bits = 0u; rn = 0u; }
        if (lane == 0) g_bits[(size_t)b * 128 + c] = bits;
        r = rn;
    }
}

// ---------------- phase A: per-chunk local ESPs ----------------
__device__ void phaseA(const float* __restrict__ scores, int xb)
{
    int lane = threadIdx.x & 31;
    int wid = xb * 4 + (threadIdx.x >> 5);   // 0..8191
    int b = wid >> 5;
    int c = wid & 31;
    const int bz = b >> 1, e = b & 1;
    const float* thbase = scores + (size_t)bz * (NN * ENS) + e;

    float F = (lane == 0) ? 0.0f : NEGC;
    int base0 = c * CLEN;
    for (int blk = 0; blk < CLEN / 32; ++blk) {
        float thv = thbase[2 * (base0 + blk * 32 + lane)];
#pragma unroll 8
        for (int ii = 0; ii < 32; ++ii) {
            float th = __shfl_sync(FULLM, thv, ii);
            float Fp = __shfl_up_sync(FULLM, F, 1);
            if (lane == 0) Fp = NEGC;
            F = logaddexp_fast(F, Fp + th);
        }
    }
    g_CE[((size_t)b * NCHUNK + c) * KK + lane] = F;
}

// ---------------- merge: chunk boundary prefixes + off ----------------
__device__ void merge_chunks(int xb)
{
    int lane = threadIdx.x & 31;
    int b = xb * 4 + (threadIdx.x >> 5);

    float P = (lane == 0) ? 0.0f : NEGC;
    for (int c = 0; c < NCHUNK; ++c) {
        g_BD[((size_t)b * NCHUNK + c) * KK + lane] = P;  // exclusive prefix
        float L = g_CE[((size_t)b * NCHUNK + c) * KK + lane];
        float mx = NEGC;
#pragma unroll
        for (int m = 0; m < 32; ++m) {
            float Pm = __shfl_sync(FULLM, P, m);
            float Lx = __shfl_sync(FULLM, L, (lane - m) & 31);
            if (m <= lane) mx = fmaxf(mx, Pm + Lx);
        }
        float sum = 0.0f;
#pragma unroll
        for (int m = 0; m < 32; ++m) {
            float Pm = __shfl_sync(FULLM, P, m);
            float Lx = __shfl_sync(FULLM, L, (lane - m) & 31);
            if (m <= lane) sum += __expf(Pm + Lx - mx);
        }
        P = mx + __logf(sum);
    }
    if (lane == 31) g_off[b] = P;   // log e_31 — early normalization offset
}

// ---------------- fused phaseC + comb ----------------
__device__ void phaseC_comb(const float* __restrict__ scores, int item,
                            int cbase, int ccnt, float* tile)
{
    int lane = threadIdx.x & 31;
    int b = item / ccnt;
    int c = cbase + (item % ccnt);
    const int bz = b >> 1, e = b & 1;
    const float* thbase = scores + (size_t)bz * (NN * ENS) + e;

    float F = g_BD[((size_t)b * NCHUNK + c) * KK + lane];   // lane j holds log e_j
    float off = g_off[b];
    int base0 = c * CLEN;

    for (int blk = 0; blk < CLEN / 32; ++blk) {
        int base = base0 + blk * 32;
        float thv = thbase[2 * (base + lane)];
#pragma unroll 8
        for (int ii = 0; ii < 32; ++ii) {
            int i = base + ii;
            float Bv = g_B[((size_t)(i + 1) * BE + b) * KK + lane];  // col lane+1
            float th = __shfl_sync(FULLM, thv, ii);
            float Brev = __shfl_sync(FULLM, Bv, (30 - lane) & 31);   // col 31-lane
            if (lane == 31) Brev = 0.0f;                             // col 0 == 0
            tile[ii * 33 + lane] = __expf(F + Brev + (th - off));
            float Fp = __shfl_up_sync(FULLM, F, 1);
            if (lane == 0) Fp = NEGC;
            F = logaddexp_fast(F, Fp + th);
        }
        __syncwarp();
        const float* row = tile + lane * 33;
        float sum = 0.0f;
#pragma unroll
        for (int j = 0; j < 32; ++j) sum += row[j];
        g_M[(size_t)b * NN + base + lane] = sum;
        __syncwarp();
    }
}

// ---------------- sliced fused kernel ----------------
__global__ void k_slice(const float* __restrict__ scores, int s)
{
    __shared__ float s_tile[4][32 * 33];   // 16.9KB; only phaseC_comb uses it

    if (blockIdx.x < BK_BLK) {
        backward_slice(scores, s);
        return;
    }
    int xb = blockIdx.x - BK_BLK;
    int wid = threadIdx.x >> 5;
    float* tile = &s_tile[wid][0];

    if (s == 0) {
        phaseA(scores, xb);                               // 2048 blocks
    } else if (s == 1) {
        if (xb < 64) merge_chunks(xb);
        else samp_chunk(xb - 64, 96);                     // chunks 96..127
    } else if (s == 2) {
        if (xb < 1024) phaseC_comb(scores, xb * 4 + wid, 16, 16, tile);
        else samp_chunk(xb - 1024, 64);                   // chunks 64..95
    } else {
        if (xb < 512) phaseC_comb(scores, xb * 4 + wid, 8, 8, tile);
        else samp_chunk(xb - 512, 32);                    // chunks 32..63
    }
}

// ---------------- tail: last phaseC_comb band + hybrid composition ----------------
__global__ void k_tail(const float* __restrict__ scores)
{
    __shared__ float s_tile[4][32 * 33];
    if (blockIdx.x < 512) {
        phaseC_comb(scores, blockIdx.x * 4 + (threadIdx.x >> 5), 0, 8,
                    &s_tile[threadIdx.x >> 5][0]);
    } else {
        comp_hybrid(blockIdx.x - 512);   // 64 blocks, warp per b
    }
}

// ---------------- finalize ----------------
__global__ void k_final(float* __restrict__ out)
{
    int tid = blockIdx.x * blockDim.x + threadIdx.x;  // 0 .. 2^20-1
    int bz = tid >> 13;
    int rem = tid & 8191;
    int n = rem >> 1;
    int e = rem & 1;
    int be = bz * ENS + e;
    float s = (float)((g_bits[(size_t)be * (NN / 32) + (n >> 5)] >> (n & 31)) & 1u);
    float m = g_M[(size_t)be * NN + n] * __expf(g_off[be] - g_logZ[be]);
    out[tid] = (s - m) + m;
    out[HALF_OUT + tid] = m;
}

extern "C" void kernel_launch(void* const* d_in, const int* in_sizes, int n_in,
                              void* d_out, int out_size)
{
    const float* scores = (const float*)d_in[0];
    float* out = (float*)d_out;
    (void)in_sizes; (void)n_in; (void)out_size;

    k_slice<<<BK_BLK + 2048,        128>>>(scores, 0);  // backward + phaseA
    k_slice<<<BK_BLK + 64 + 2048,   128>>>(scores, 1);  // backward + merge + sc 96-127
    k_slice<<<BK_BLK + 1024 + 2048, 128>>>(scores, 2);  // backward + PC 16-31 + sc 64-95
    k_slice<<<BK_BLK + 512 + 2048,  128>>>(scores, 3);  // backward + PC 8-15  + sc 32-63
    k_tail<<<576, 128>>>(scores);                       // PC 0-7 + hybrid comp
    k_final<<<2048, 512>>>(out);
}

// round 17
// speedup vs baseline: 1.8658x; 1.8658x over previous
#include <cuda_runtime.h>
#include <stdint.h>
#include <math.h>

// Problem constants (fixed shapes: scores (128, 4096, 2))
#define NN   4096
#define BSZ  128
#define ENS  2
#define BE   256           // BSZ*ENS
#define KK   32
#define NEGC (-1e30f)
#define HALF_OUT 1048576   // 128*4096*2
#define NCHUNK 32
#define CLEN   128         // NN / NCHUNK
#define NSLICE 4
#define SLEN   1024        // NN / NSLICE
#define FULLM  0xffffffffu

// ---------------- scratch (static device memory) ----------------
__device__ float    g_B[(size_t)(NN + 1) * BE * KK]; // B[i][b][j-1]
__device__ unsigned g_mask[(size_t)BE * NN];         // inclusion masks [b*NN + i]
__device__ float    g_CE[(size_t)BE * NCHUNK * KK];  // chunk ESPs
__device__ float    g_BD[(size_t)BE * NCHUNK * KK];  // chunk boundary prefixes
__device__ float    g_M[(size_t)BE * NN];            // unnormalized marginals [b][i]
__device__ float    g_E[(size_t)BE * KK];            // backward state between slices
__device__ float    g_off[BE];                       // log e_31 (early normalizer)
__device__ float    g_logZ[BE];                      // exact log e_32
__device__ unsigned g_bits[(size_t)BE * (NN / 32)];  // sampled bits
// sampler chunk-function tables (chunks 32..127)
__device__ unsigned g_sampBits[(size_t)BE * 128 * 32];
__device__ unsigned g_sampMap[(size_t)BE * 128 * 32];

// ---------------- threefry2x32, key = (0, 42) ----------------
__device__ __forceinline__ uint32_t tf_bits(uint32_t lo)
{
    uint32_t x0 = 0u;
    uint32_t x1 = lo;
    const uint32_t ks0 = 0u, ks1 = 42u, ks2 = 0x1BD11BF0u;
    x0 += ks0; x1 += ks1;
#define TFR(r) { x0 += x1; x1 = (x1 << (r)) | (x1 >> (32 - (r))); x1 ^= x0; }
    TFR(13) TFR(15) TFR(26) TFR(6)   x0 += ks1; x1 += ks2 + 1u;
    TFR(17) TFR(29) TFR(16) TFR(24)  x0 += ks2; x1 += ks0 + 2u;
    TFR(13) TFR(15) TFR(26) TFR(6)   x0 += ks0; x1 += ks1 + 3u;
    TFR(17) TFR(29) TFR(16) TFR(24)  x0 += ks1; x1 += ks2 + 4u;
    TFR(13) TFR(15) TFR(26) TFR(6)   x0 += ks2; x1 += ks0 + 5u;
#undef TFR
    return x0 ^ x1;
}

// EXACT logaddexp (libdevice — bitwise path for sampling masks)
__device__ __forceinline__ float logaddexpf32(float x, float y)
{
    float d = x - y;
    return fmaxf(x, y) + log1pf(expf(-fabsf(d)));
}

// Fast logaddexp (marginals path, 1e-3 tolerance)
__device__ __forceinline__ float logaddexp_fast(float x, float y)
{
    float d = x - y;
    return fmaxf(x, y) + __logf(1.0f + __expf(-fabsf(d)));
}

// ---------------- backward slice (exact chain, DEFERRED ballots) ----------------
// R13/R15 chain verbatim: 1024 rows per slice (32 blocks of 32 steps).
__device__ void backward_slice(const float* __restrict__ scores, int s)
{
    int lane = threadIdx.x & 31;
    int b = blockIdx.x * 4 + (threadIdx.x >> 5);
    const int bz = b >> 1, e = b & 1;
    const float* thbase = scores + (size_t)bz * (NN * ENS) + e;

    float E;
    if (s == 0) {
        E = NEGC;
        g_B[((size_t)NN * BE + b) * KK + lane] = NEGC;   // init row (i = NN)
    } else {
        E = g_E[(size_t)b * KK + lane];
    }

    int blk_hi = (NN / 32) - 32 * s;        // exclusive
    int blk_lo = blk_hi - 32;

    // prefetch theta for the first block of this slice
    float thv = thbase[2 * ((blk_hi - 1) * 32 + lane)];

    for (int blk = blk_hi - 1; blk >= blk_lo; --blk) {
        int base = blk * 32;
        float thv_next = (blk > blk_lo) ? thbase[2 * ((blk - 1) * 32 + lane)] : 0.0f;
        // inline threefry uniform (bit-identical to jax.random.uniform, index i*BE+b)
        uint32_t rb = tf_bits((uint32_t)((base + lane) * BE + b));
        float uv = fmaxf(__uint_as_float((rb >> 9) | 0x3f800000u) - 1.0f, 0.0f);

#pragma unroll
        for (int g8 = 3; g8 >= 0; --g8) {
            float lq[8];
            // chain segment: 8 exact steps; ballots deferred (off critical path)
#pragma unroll
            for (int t = 7; t >= 0; --t) {
                int ii = g8 * 8 + t;
                float th = __shfl_sync(FULLM, thv, ii);
                float Ep = __shfl_up_sync(FULLM, E, 1);
                if (lane == 0) Ep = 0.0f;
                float shifted = Ep + th;
                float Enew = logaddexpf32(E, shifted);
                lq[t] = shifted - Enew;       // logq, buffered
                E = Enew;
                g_B[((size_t)(base + ii) * BE + b) * KK + lane] = E;
            }
            // deferred mask generation: 8 independent expf+ballot, pipelined
#pragma unroll
            for (int t = 7; t >= 0; --t) {
                int ii = g8 * 8 + t;
                float u = __shfl_sync(FULLM, uv, ii);
                float q = expf(fminf(lq[t], 0.0f));
                unsigned m = __ballot_sync(FULLM, u < q);
                if (lane == 0) g_mask[(size_t)b * NN + base + ii] = m;
            }
        }
        thv = thv_next;
    }

    if (s < NSLICE - 1) {
        g_E[(size_t)b * KK + lane] = E;
    } else {
        float lz = __shfl_sync(FULLM, E, 31);   // B[0][b][32] = logZ
        if (lane == 0) g_logZ[b] = lz;
    }
}

// ---------------- sampler chunk-function evaluation (32-chunk bands) ----------------
__device__ void samp_chunk(int xb, int cbase)
{
    int lane = threadIdx.x & 31;
    int item = xb * 4 + (threadIdx.x >> 5);   // 0..8191
    int b = item >> 5;
    int c = cbase + (item & 31);

    unsigned mv = g_mask[(size_t)b * NN + c * 32 + lane];  // coalesced
    unsigned r = (unsigned)(lane + 1);
    unsigned w = 0u;
#pragma unroll
    for (int ii = 0; ii < 32; ++ii) {
        unsigned m = __shfl_sync(FULLM, mv, ii);
        unsigned incl = r ? ((m >> (r - 1u)) & 1u) : 0u;
        r -= incl;
        w |= incl << ii;
    }
    g_sampBits[((size_t)b * 128 + c) * 32 + lane] = w;
    g_sampMap[((size_t)b * 128 + c) * 32 + lane] = r;
}

// ---------------- sampler composition (hybrid): warp per b ----------------
// Chunks 0..31 inlined from fresh masks (slice 3); chunks 32..127 from tables.
__device__ void comp_hybrid(int xb)
{
    int lane = threadIdx.x & 31;
    int b = xb * 4 + (threadIdx.x >> 5);
    const unsigned* mp = &g_sampMap[(size_t)b * 128 * 32];
    const unsigned* bp = &g_sampBits[(size_t)b * 128 * 32];

    unsigned r = KK;   // warp-uniform live state

    for (int c = 0; c < 32; ++c) {
        unsigned mv = g_mask[(size_t)b * NN + c * 32 + lane];
        unsigned rr = (unsigned)(lane + 1);
        unsigned w = 0u;
#pragma unroll
        for (int ii = 0; ii < 32; ++ii) {
            unsigned m = __shfl_sync(FULLM, mv, ii);
            unsigned incl = rr ? ((m >> (rr - 1u)) & 1u) : 0u;
            rr -= incl;
            w |= incl << ii;
        }
        unsigned idx = r ? (r - 1u) : 0u;
        unsigned bits = __shfl_sync(FULLM, w, idx);
        unsigned rn   = __shfl_sync(FULLM, rr, idx);
        if (!r) { bits = 0u; rn = 0u; }
        if (lane == 0) g_bits[(size_t)b * 128 + c] = bits;
        r = rn;
    }

#pragma unroll 4
    for (int c = 32; c < 128; ++c) {
        unsigned mapv = mp[c * 32 + lane];
        unsigned bitv = bp[c * 32 + lane];
        unsigned idx = r ? (r - 1u) : 0u;
        unsigned bits = __shfl_sync(FULLM, bitv, idx);
        unsigned rn   = __shfl_sync(FULLM, mapv, idx);
        if (!r) { bits = 0u; rn = 0u; }
        if (lane == 0) g_bits[(size_t)b * 128 + c] = bits;
        r = rn;
    }
}

// ---------------- phase A: per-chunk local ESPs ----------------
__device__ void phaseA(const float* __restrict__ scores, int xb)
{
    int lane = threadIdx.x & 31;
    int wid = xb * 4 + (threadIdx.x >> 5);   // 0..8191
    int b = wid >> 5;
    int c = wid & 31;
    const int bz = b >> 1, e = b & 1;
    const float* thbase = scores + (size_t)bz * (NN * ENS) + e;

    float F = (lane == 0) ? 0.0f : NEGC;
    int base0 = c * CLEN;
    for (int blk = 0; blk < CLEN / 32; ++blk) {
        float thv = thbase[2 * (base0 + blk * 32 + lane)];
#pragma unroll 8
        for (int ii = 0; ii < 32; ++ii) {
            float th = __shfl_sync(FULLM, thv, ii);
            float Fp = __shfl_up_sync(FULLM, F, 1);
            if (lane == 0) Fp = NEGC;
            F = logaddexp_fast(F, Fp + th);
        }
    }
    g_CE[((size_t)b * NCHUNK + c) * KK + lane] = F;
}

// ---------------- merge: chunk boundary prefixes + off ----------------
__device__ void merge_chunks(int xb)
{
    int lane = threadIdx.x & 31;
    int b = xb * 4 + (threadIdx.x >> 5);

    float P = (lane == 0) ? 0.0f : NEGC;
    for (int c = 0; c < NCHUNK; ++c) {
        g_BD[((size_t)b * NCHUNK + c) * KK + lane] = P;  // exclusive prefix
        float L = g_CE[((size_t)b * NCHUNK + c) * KK + lane];
        float mx = NEGC;
#pragma unroll
        for (int m = 0; m < 32; ++m) {
            float Pm = __shfl_sync(FULLM, P, m);
            float Lx = __shfl_sync(FULLM, L, (lane - m) & 31);
            if (m <= lane) mx = fmaxf(mx, Pm + Lx);
        }
        float sum = 0.0f;
#pragma unroll
        for (int m = 0; m < 32; ++m) {
            float Pm = __shfl_sync(FULLM, P, m);
            float Lx = __shfl_sync(FULLM, L, (lane - m) & 31);
            if (m <= lane) sum += __expf(Pm + Lx - mx);
        }
        P = mx + __logf(sum);
    }
    if (lane == 31) g_off[b] = P;   // log e_31 — early normalization offset
}

// ---------------- fused phaseC + comb ----------------
__device__ void phaseC_comb(const float* __restrict__ scores, int item,
                            int cbase, int ccnt, float* tile)
{
    int lane = threadIdx.x & 31;
    int b = item / ccnt;
    int c = cbase + (item % ccnt);
    const int bz = b >> 1, e = b & 1;
    const float* thbase = scores + (size_t)bz * (NN * ENS) + e;

    float F = g_BD[((size_t)b * NCHUNK + c) * KK + lane];   // lane j holds log e_j
    float off = g_off[b];
    int base0 = c * CLEN;

    for (int blk = 0; blk < CLEN / 32; ++blk) {
        int base = base0 + blk * 32;
        float thv = thbase[2 * (base + lane)];
#pragma unroll 8
        for (int ii = 0; ii < 32; ++ii) {
            int i = base + ii;
            float Bv = g_B[((size_t)(i + 1) * BE + b) * KK + lane];  // col lane+1
            float th = __shfl_sync(FULLM, thv, ii);
            float Brev = __shfl_sync(FULLM, Bv, (30 - lane) & 31);   // col 31-lane
            if (lane == 31) Brev = 0.0f;                             // col 0 == 0
            tile[ii * 33 + lane] = __expf(F + Brev + (th - off));
            float Fp = __shfl_up_sync(FULLM, F, 1);
            if (lane == 0) Fp = NEGC;
            F = logaddexp_fast(F, Fp + th);
        }
        __syncwarp();
        const float* row = tile + lane * 33;
        float sum = 0.0f;
#pragma unroll
        for (int j = 0; j < 32; ++j) sum += row[j];
        g_M[(size_t)b * NN + base + lane] = sum;
        __syncwarp();
    }
}

// ---------------- sliced fused kernel ----------------
__global__ void k_slice(const float* __restrict__ scores, int s)
{
    __shared__ float s_tile[4][32 * 33];   // 16.9KB; only phaseC_comb uses it

    if (blockIdx.x < 64) {
        backward_slice(scores, s);
        return;
    }
    int xb = blockIdx.x - 64;
    int wid = threadIdx.x >> 5;
    float* tile = &s_tile[wid][0];

    if (s == 0) {
        phaseA(scores, xb);                               // 2048 blocks
    } else if (s == 1) {
        if (xb < 64) merge_chunks(xb);
        else samp_chunk(xb - 64, 96);                     // chunks 96..127
    } else if (s == 2) {
        if (xb < 1024) phaseC_comb(scores, xb * 4 + wid, 16, 16, tile);
        else samp_chunk(xb - 1024, 64);                   // chunks 64..95
    } else {
        if (xb < 512) phaseC_comb(scores, xb * 4 + wid, 8, 8, tile);
        else samp_chunk(xb - 512, 32);                    // chunks 32..63
    }
}

// ---------------- tail: last phaseC_comb band + hybrid composition ----------------
__global__ void k_tail(const float* __restrict__ scores)
{
    __shared__ float s_tile[4][32 * 33];
    if (blockIdx.x < 512) {
        phaseC_comb(scores, blockIdx.x * 4 + (threadIdx.x >> 5), 0, 8,
                    &s_tile[threadIdx.x >> 5][0]);
    } else {
        comp_hybrid(blockIdx.x - 512);   // 64 blocks, warp per b
    }
}

// ---------------- finalize (coalesced: thread per (bz, n), both ensemble slots) ----
__global__ void k_final(float* __restrict__ out)
{
    int tid = blockIdx.x * blockDim.x + threadIdx.x;  // 0 .. 2^19-1
    int bz = tid >> 12;
    int n  = tid & (NN - 1);
    int b0 = bz * 2, b1 = b0 + 1;

    // coalesced row reads (warp = 32 consecutive n within one b-row)
    float m0 = g_M[(size_t)b0 * NN + n] * __expf(g_off[b0] - g_logZ[b0]);
    float m1 = g_M[(size_t)b1 * NN + n] * __expf(g_off[b1] - g_logZ[b1]);
    // warp-broadcast bit words
    float s0 = (float)((g_bits[(size_t)b0 * 128 + (n >> 5)] >> (n & 31)) & 1u);
    float s1 = (float)((g_bits[(size_t)b1 * 128 + (n >> 5)] >> (n & 31)) & 1u);

    size_t o = (size_t)bz * (NN * ENS) + n * 2;
    *(float2*)&out[o]            = make_float2((s0 - m0) + m0, (s1 - m1) + m1);
    *(float2*)&out[HALF_OUT + o] = make_float2(m0, m1);
}

extern "C" void kernel_launch(void* const* d_in, const int* in_sizes, int n_in,
                              void* d_out, int out_size)
{
    const float* scores = (const float*)d_in[0];
    float* out = (float*)d_out;
    (void)in_sizes; (void)n_in; (void)out_size;

    k_slice<<<64 + 2048,        128>>>(scores, 0);  // backward + phaseA
    k_slice<<<64 + 64 + 2048,   128>>>(scores, 1);  // backward + merge + sc 96-127
    k_slice<<<64 + 1024 + 2048, 128>>>(scores, 2);  // backward + PC 16-31 + sc 64-95
    k_slice<<<64 + 512 + 2048,  128>>>(scores, 3);  // backward + PC 8-15  + sc 32-63
    k_tail<<<576, 128>>>(scores);                   // PC 0-7 + hybrid comp
    k_final<<<1024, 512>>>(out);
}